// round 4
// baseline (speedup 1.0000x reference)
#include <cuda_runtime.h>

#define B_ 4
#define N_ 2048
#define C_ 1024
#define H_ 16
#define HD_ 64
#define BH_ (B_ * H_)

// Scratch (allocation-free rule: __device__ globals)
__device__ float g_q[BH_ * N_ * HD_];           // 32 MB, pre-scaled by hd^-0.5
__device__ float g_k[BH_ * N_ * HD_];           // 32 MB
__device__ float g_v[BH_ * N_ * HD_];           // 32 MB
__device__ float g_s[268435456];                // B*H*N*N = 1 GB attention matrix
__device__ float g_ao[B_ * N_ * C_];            // 32 MB attention output [B,N,C]

// ---------------------------------------------------------------------------
// QKV projection: x[8192,1024] @ W_qkv[1024,3072] -> q/k/v in [B,H,N,hd]
// 128x128 tile, BK=8, 8x8 microtile (strided by 16 for conflict-free LDS)
// ---------------------------------------------------------------------------
__global__ __launch_bounds__(256, 2) void qkv_gemm(const float* __restrict__ x,
                                                   const float* __restrict__ w) {
    __shared__ float As[8][128];
    __shared__ float Bs[8][128];
    const int bm = blockIdx.y << 7;
    const int bn = blockIdx.x << 7;
    const int tid = threadIdx.x;
    const int ty = tid >> 4, tx = tid & 15;
    const int arow = tid >> 1, acol = (tid & 1) << 2;
    const int brow = tid >> 5, bcol = (tid & 31) << 2;

    float acc[8][8];
#pragma unroll
    for (int i = 0; i < 8; i++)
#pragma unroll
        for (int j = 0; j < 8; j++) acc[i][j] = 0.f;

    const float* Ap = x + (size_t)(bm + arow) * C_ + acol;
    const float* Bp = w + (size_t)brow * 3072 + bn + bcol;

    for (int k0 = 0; k0 < C_; k0 += 8) {
        float4 a4 = *(const float4*)(Ap + k0);
        As[acol + 0][arow] = a4.x;
        As[acol + 1][arow] = a4.y;
        As[acol + 2][arow] = a4.z;
        As[acol + 3][arow] = a4.w;
        *(float4*)&Bs[brow][bcol] = *(const float4*)(Bp + (size_t)k0 * 3072);
        __syncthreads();
#pragma unroll
        for (int k = 0; k < 8; k++) {
            float a[8], b[8];
#pragma unroll
            for (int i = 0; i < 8; i++) a[i] = As[k][ty + 16 * i];
#pragma unroll
            for (int j = 0; j < 8; j++) b[j] = Bs[k][tx + 16 * j];
#pragma unroll
            for (int i = 0; i < 8; i++)
#pragma unroll
                for (int j = 0; j < 8; j++) acc[i][j] = fmaf(a[i], b[j], acc[i][j]);
        }
        __syncthreads();
    }

#pragma unroll
    for (int i = 0; i < 8; i++) {
        int m = bm + ty + 16 * i;            // global row = b*N + n
        int b = m >> 11, n = m & (N_ - 1);
#pragma unroll
        for (int j = 0; j < 8; j++) {
            int col = bn + tx + 16 * j;      // 0..3071
            int part = col >> 10;            // 0=q 1=k 2=v
            int c = col & (C_ - 1);
            int h = c >> 6, d = c & 63;
            size_t idx = ((size_t)(b * H_ + h) * N_ + n) * HD_ + d;
            float v = acc[i][j];
            if (part == 0)      g_q[idx] = v * 0.125f;   // scale = 64^-0.5
            else if (part == 1) g_k[idx] = v;
            else                g_v[idx] = v;
        }
    }
}

// ---------------------------------------------------------------------------
// S = Q @ K^T + mask_bias, per (b,h). 64x64 tile, K=64 fully resident.
// ---------------------------------------------------------------------------
__global__ __launch_bounds__(256) void s_gemm(const int* __restrict__ mask) {
    __shared__ float Qt[HD_][65];
    __shared__ float Kt[HD_][65];
    const int bh = blockIdx.z;
    const int b = bh >> 4;
    const int i0 = blockIdx.y << 6;
    const int j0 = blockIdx.x << 6;
    const float* Q = g_q + (size_t)bh * N_ * HD_;
    const float* K = g_k + (size_t)bh * N_ * HD_;
    const int tid = threadIdx.x;
    const int lr = tid >> 2, lc = (tid & 3) << 4;

#pragma unroll
    for (int t = 0; t < 4; t++) {
        float4 q4 = *(const float4*)(Q + (size_t)(i0 + lr) * HD_ + lc + 4 * t);
        Qt[lc + 4 * t + 0][lr] = q4.x;
        Qt[lc + 4 * t + 1][lr] = q4.y;
        Qt[lc + 4 * t + 2][lr] = q4.z;
        Qt[lc + 4 * t + 3][lr] = q4.w;
        float4 k4 = *(const float4*)(K + (size_t)(j0 + lr) * HD_ + lc + 4 * t);
        Kt[lc + 4 * t + 0][lr] = k4.x;
        Kt[lc + 4 * t + 1][lr] = k4.y;
        Kt[lc + 4 * t + 2][lr] = k4.z;
        Kt[lc + 4 * t + 3][lr] = k4.w;
    }
    __syncthreads();

    const int ty = tid >> 4, tx = tid & 15;
    float acc[4][4];
#pragma unroll
    for (int i = 0; i < 4; i++)
#pragma unroll
        for (int j = 0; j < 4; j++) acc[i][j] = 0.f;

#pragma unroll 8
    for (int d = 0; d < HD_; d++) {
        float a[4], bb[4];
#pragma unroll
        for (int i = 0; i < 4; i++) a[i] = Qt[d][ty + 16 * i];
#pragma unroll
        for (int j = 0; j < 4; j++) bb[j] = Kt[d][tx + 16 * j];
#pragma unroll
        for (int i = 0; i < 4; i++)
#pragma unroll
            for (int j = 0; j < 4; j++) acc[i][j] = fmaf(a[i], bb[j], acc[i][j]);
    }

    float* S = g_s + (size_t)bh * N_ * N_;
    float bias[4];
#pragma unroll
    for (int j = 0; j < 4; j++) {
        int col = j0 + tx + 16 * j;
        bias[j] = (mask[b * N_ + col] != 1) ? -10000.0f : 0.0f;
    }
#pragma unroll
    for (int i = 0; i < 4; i++) {
        int row = i0 + ty + 16 * i;
#pragma unroll
        for (int j = 0; j < 4; j++)
            S[(size_t)row * N_ + j0 + tx + 16 * j] = acc[i][j] + bias[j];
    }
}

// ---------------------------------------------------------------------------
// Row softmax over 2048 keys. One block per (b,h,q) row; 8 values/thread.
// ---------------------------------------------------------------------------
__global__ __launch_bounds__(256) void softmax_k() {
    const size_t row = blockIdx.x;
    float* p = g_s + row * N_;
    const int tid = threadIdx.x;
    float4 v0 = *(const float4*)(p + tid * 8);
    float4 v1 = *(const float4*)(p + tid * 8 + 4);

    float m = fmaxf(fmaxf(fmaxf(v0.x, v0.y), fmaxf(v0.z, v0.w)),
                    fmaxf(fmaxf(v1.x, v1.y), fmaxf(v1.z, v1.w)));
#pragma unroll
    for (int o = 16; o > 0; o >>= 1) m = fmaxf(m, __shfl_xor_sync(0xffffffffu, m, o));
    __shared__ float red_m[8];
    __shared__ float red_s[8];
    if ((tid & 31) == 0) red_m[tid >> 5] = m;
    __syncthreads();
    m = red_m[0];
#pragma unroll
    for (int i = 1; i < 8; i++) m = fmaxf(m, red_m[i]);

    v0.x = __expf(v0.x - m); v0.y = __expf(v0.y - m);
    v0.z = __expf(v0.z - m); v0.w = __expf(v0.w - m);
    v1.x = __expf(v1.x - m); v1.y = __expf(v1.y - m);
    v1.z = __expf(v1.z - m); v1.w = __expf(v1.w - m);
    float s = v0.x + v0.y + v0.z + v0.w + v1.x + v1.y + v1.z + v1.w;
#pragma unroll
    for (int o = 16; o > 0; o >>= 1) s += __shfl_xor_sync(0xffffffffu, s, o);
    if ((tid & 31) == 0) red_s[tid >> 5] = s;
    __syncthreads();
    s = red_s[0];
#pragma unroll
    for (int i = 1; i < 8; i++) s += red_s[i];

    float r = 1.0f / s;
    v0.x *= r; v0.y *= r; v0.z *= r; v0.w *= r;
    v1.x *= r; v1.y *= r; v1.z *= r; v1.w *= r;
    *(float4*)(p + tid * 8) = v0;
    *(float4*)(p + tid * 8 + 4) = v1;
}

// ---------------------------------------------------------------------------
// O = P @ V per (b,h): [2048,2048] @ [2048,64]. 64x64 tile, BK=16.
// Writes to g_ao in [B,N,C] layout (c = h*64+d).
// ---------------------------------------------------------------------------
__global__ __launch_bounds__(256) void pv_gemm() {
    __shared__ float Pt[16][64];
    __shared__ float Vt[16][64];
    const int bh = blockIdx.y;
    const int b = bh >> 4, h = bh & 15;
    const int i0 = blockIdx.x << 6;
    const float* P = g_s + (size_t)bh * N_ * N_;
    const float* V = g_v + (size_t)bh * N_ * HD_;
    const int tid = threadIdx.x;
    const int prow = tid >> 2, pk = (tid & 3) << 2;
    const int vrow = tid >> 4, vcol = (tid & 15) << 2;
    const int ty = tid >> 4, tx = tid & 15;

    float acc[4][4];
#pragma unroll
    for (int i = 0; i < 4; i++)
#pragma unroll
        for (int j = 0; j < 4; j++) acc[i][j] = 0.f;

    for (int k0 = 0; k0 < N_; k0 += 16) {
        float4 p4 = *(const float4*)(P + (size_t)(i0 + prow) * N_ + k0 + pk);
        Pt[pk + 0][prow] = p4.x;
        Pt[pk + 1][prow] = p4.y;
        Pt[pk + 2][prow] = p4.z;
        Pt[pk + 3][prow] = p4.w;
        *(float4*)&Vt[vrow][vcol] = *(const float4*)(V + (size_t)(k0 + vrow) * HD_ + vcol);
        __syncthreads();
#pragma unroll
        for (int k = 0; k < 16; k++) {
            float a[4], bb[4];
#pragma unroll
            for (int i = 0; i < 4; i++) a[i] = Pt[k][ty + 16 * i];
#pragma unroll
            for (int j = 0; j < 4; j++) bb[j] = Vt[k][tx + 16 * j];
#pragma unroll
            for (int i = 0; i < 4; i++)
#pragma unroll
                for (int j = 0; j < 4; j++) acc[i][j] = fmaf(a[i], bb[j], acc[i][j]);
        }
        __syncthreads();
    }

#pragma unroll
    for (int i = 0; i < 4; i++) {
        int n = i0 + ty + 16 * i;
#pragma unroll
        for (int j = 0; j < 4; j++) {
            int d = tx + 16 * j;
            g_ao[(size_t)(b * N_ + n) * C_ + h * HD_ + d] = acc[i][j];
        }
    }
}

// ---------------------------------------------------------------------------
// Output projection: g_ao[8192,1024] @ W_proj[1024,1024] + b_proj -> d_out
// ---------------------------------------------------------------------------
__global__ __launch_bounds__(256, 2) void proj_gemm(const float* __restrict__ w,
                                                    const float* __restrict__ bias,
                                                    float* __restrict__ out) {
    __shared__ float As[8][128];
    __shared__ float Bs[8][128];
    const int bm = blockIdx.y << 7;
    const int bn = blockIdx.x << 7;
    const int tid = threadIdx.x;
    const int ty = tid >> 4, tx = tid & 15;
    const int arow = tid >> 1, acol = (tid & 1) << 2;
    const int brow = tid >> 5, bcol = (tid & 31) << 2;

    float acc[8][8];
#pragma unroll
    for (int i = 0; i < 8; i++)
#pragma unroll
        for (int j = 0; j < 8; j++) acc[i][j] = 0.f;

    const float* Ap = g_ao + (size_t)(bm + arow) * C_ + acol;
    const float* Bp = w + (size_t)brow * C_ + bn + bcol;

    for (int k0 = 0; k0 < C_; k0 += 8) {
        float4 a4 = *(const float4*)(Ap + k0);
        As[acol + 0][arow] = a4.x;
        As[acol + 1][arow] = a4.y;
        As[acol + 2][arow] = a4.z;
        As[acol + 3][arow] = a4.w;
        *(float4*)&Bs[brow][bcol] = *(const float4*)(Bp + (size_t)k0 * C_);
        __syncthreads();
#pragma unroll
        for (int k = 0; k < 8; k++) {
            float a[8], b[8];
#pragma unroll
            for (int i = 0; i < 8; i++) a[i] = As[k][ty + 16 * i];
#pragma unroll
            for (int j = 0; j < 8; j++) b[j] = Bs[k][tx + 16 * j];
#pragma unroll
            for (int i = 0; i < 8; i++)
#pragma unroll
                for (int j = 0; j < 8; j++) acc[i][j] = fmaf(a[i], b[j], acc[i][j]);
        }
        __syncthreads();
    }

#pragma unroll
    for (int i = 0; i < 8; i++) {
        int m = bm + ty + 16 * i;
#pragma unroll
        for (int j = 0; j < 8; j++) {
            int col = bn + tx + 16 * j;
            out[(size_t)m * C_ + col] = acc[i][j] + bias[col];
        }
    }
}

// ---------------------------------------------------------------------------
extern "C" void kernel_launch(void* const* d_in, const int* in_sizes, int n_in,
                              void* d_out, int out_size) {
    const float* x     = (const float*)d_in[0];
    const int*   mask  = (const int*)d_in[1];
    const float* wqkv  = (const float*)d_in[2];
    const float* wproj = (const float*)d_in[3];
    const float* bproj = (const float*)d_in[4];
    float* out = (float*)d_out;

    qkv_gemm<<<dim3(24, 64), 256>>>(x, wqkv);            // 3072/128 x 8192/128
    s_gemm<<<dim3(32, 32, 64), 256>>>(mask);             // N/64 x N/64 x B*H
    softmax_k<<<BH_ * N_, 256>>>();                      // one block per row
    pv_gemm<<<dim3(32, 64), 256>>>();                    // N/64 x B*H
    proj_gemm<<<dim3(8, 64), 256>>>(wproj, bproj, out);  // 1024/128 x 8192/128
}

// round 5
// speedup vs baseline: 2.3321x; 2.3321x over previous
#include <cuda_runtime.h>
#include <cstdint>

#define B_ 4
#define N_ 2048
#define C_ 1024
#define H_ 16
#define HD_ 64
#define BH_ (B_ * H_)

// Scratch (allocation-free rule: __device__ globals)
__device__ float g_q[BH_ * N_ * HD_];           // pre-scaled by hd^-0.5
__device__ float g_k[BH_ * N_ * HD_];
__device__ float g_v[BH_ * N_ * HD_];
__device__ float g_s[268435456];                // B*H*N*N attention matrix (1 GB)
__device__ float g_ao[B_ * N_ * C_];            // attention output [B,N,C]

__device__ __forceinline__ float to_tf32(float x) {
    float r;
    asm("cvt.rna.tf32.f32 %0, %1;" : "=f"(r) : "f"(x));
    return r;
}

// ---------------------------------------------------------------------------
// Generic tf32 tensor-core GEMM.
//   C[M,N] = A[M,K] @ B[K,N]   (TB=false: B row-major K x N)
//                              (TB=true : B given as N x K row-major, used as B^T)
// Block tile BM x BN x BK, 256 threads (8 warps), warp tile (BM/WARPS_M) x (BN/WARPS_N)
// built from m16n8k8 tf32 mma atoms.  EPI selects operand sources + epilogue.
//   EPI 0: qkv   A=x,      B=W_qkv -> scatter q(*0.125)/k/v
//   EPI 1: s     A=g_q[bh], B=g_k[bh] (TB) -> g_s + mask bias
//   EPI 2: pv    A=g_s[bh], B=g_v[bh]      -> g_ao scatter
//   EPI 3: proj  A=g_ao,   B=W_proj        -> out + bias
// ---------------------------------------------------------------------------
template <int BM, int BN, int BK, int WARPS_M, int WARPS_N, bool TB, int EPI>
__global__ __launch_bounds__(256) void tf32_gemm(
    const float* __restrict__ gA, const float* __restrict__ gB,
    const int* __restrict__ mask, const float* __restrict__ bias,
    float* __restrict__ gC, int M, int N, int K)
{
    constexpr int WM = BM / WARPS_M;
    constexpr int WN = BN / WARPS_N;
    constexpr int MA = WM / 16;          // m-atoms per warp
    constexpr int NA = WN / 8;           // n-atoms per warp
    constexpr int PAD = 8;
    constexpr int AL = BM * BK / 1024;   // float4 per thread for A tile
    constexpr int BL = BK * BN / 1024;   // float4 per thread for B tile

    __shared__ float As[BK][BM + PAD];
    __shared__ float Bs[BK][BN + PAD];

    const int tid = threadIdx.x;
    const int warp = tid >> 5, lane = tid & 31;
    const int g = lane >> 2, tg = lane & 3;
    const int wm0 = (warp / WARPS_N) * WM;
    const int wn0 = (warp % WARPS_N) * WN;
    const int bm = blockIdx.y * BM;
    const int bn = blockIdx.x * BN;
    const int bh = blockIdx.z;

    const float* A;
    const float* Bm;
    int lda, ldb;
    if constexpr (EPI == 0)      { A = gA;                              lda = K;   Bm = gB;                              ldb = N;   }
    else if constexpr (EPI == 1) { A = g_q + (size_t)bh * N_ * HD_;     lda = HD_; Bm = g_k + (size_t)bh * N_ * HD_;     ldb = HD_; }
    else if constexpr (EPI == 2) { A = g_s + (size_t)bh * N_ * N_;      lda = N_;  Bm = g_v + (size_t)bh * N_ * HD_;     ldb = HD_; }
    else                         { A = g_ao;                            lda = K;   Bm = gB;                              ldb = N;   }

    // A fill mapping: (am, ak+8l) transpose-store to As[k][m]
    const int am = tid >> 1;
    const int ak = (tid & 1) * 4;
    // B fill mapping (row-major case)
    constexpr int BCOLS4 = BN / 4;
    constexpr int BROWSTEP = 256 / BCOLS4;
    const int bRow0 = tid / BCOLS4;
    const int bCol = (tid % BCOLS4) * 4;

    float4 aR[AL], bR[BL];

    auto loadA = [&](int k0) {
#pragma unroll
        for (int l = 0; l < AL; l++)
            aR[l] = *(const float4*)(A + (size_t)(bm + am) * lda + k0 + ak + 8 * l);
    };
    auto loadB = [&](int k0) {
        if constexpr (!TB) {
#pragma unroll
            for (int l = 0; l < BL; l++)
                bR[l] = *(const float4*)(Bm + (size_t)(k0 + bRow0 + BROWSTEP * l) * ldb + bn + bCol);
        } else {
#pragma unroll
            for (int l = 0; l < BL; l++)
                bR[l] = *(const float4*)(Bm + (size_t)(bn + am) * ldb + k0 + ak + 8 * l);
        }
    };
    auto storeSmem = [&]() {
#pragma unroll
        for (int l = 0; l < AL; l++) {
            As[ak + 8 * l + 0][am] = to_tf32(aR[l].x);
            As[ak + 8 * l + 1][am] = to_tf32(aR[l].y);
            As[ak + 8 * l + 2][am] = to_tf32(aR[l].z);
            As[ak + 8 * l + 3][am] = to_tf32(aR[l].w);
        }
        if constexpr (!TB) {
#pragma unroll
            for (int l = 0; l < BL; l++) {
                float4 w;
                w.x = to_tf32(bR[l].x); w.y = to_tf32(bR[l].y);
                w.z = to_tf32(bR[l].z); w.w = to_tf32(bR[l].w);
                *(float4*)&Bs[bRow0 + BROWSTEP * l][bCol] = w;
            }
        } else {
#pragma unroll
            for (int l = 0; l < BL; l++) {
                Bs[ak + 8 * l + 0][am] = to_tf32(bR[l].x);
                Bs[ak + 8 * l + 1][am] = to_tf32(bR[l].y);
                Bs[ak + 8 * l + 2][am] = to_tf32(bR[l].z);
                Bs[ak + 8 * l + 3][am] = to_tf32(bR[l].w);
            }
        }
    };

    float acc[MA][NA][4];
#pragma unroll
    for (int i = 0; i < MA; i++)
#pragma unroll
        for (int j = 0; j < NA; j++)
#pragma unroll
            for (int r = 0; r < 4; r++) acc[i][j][r] = 0.f;

    const int kTiles = K / BK;
    loadA(0);
    loadB(0);
    storeSmem();
    __syncthreads();

    for (int t = 0; t < kTiles; ++t) {
        if (t + 1 < kTiles) {
            loadA((t + 1) * BK);
            loadB((t + 1) * BK);
        }
        // compute over resident smem tile
#pragma unroll
        for (int ks = 0; ks < BK / 8; ks++) {
            uint32_t af[MA][4], bf[NA][2];
            const int kb = ks * 8 + tg;
#pragma unroll
            for (int i = 0; i < MA; i++) {
                af[i][0] = __float_as_uint(As[kb][wm0 + i * 16 + g]);
                af[i][1] = __float_as_uint(As[kb][wm0 + i * 16 + g + 8]);
                af[i][2] = __float_as_uint(As[kb + 4][wm0 + i * 16 + g]);
                af[i][3] = __float_as_uint(As[kb + 4][wm0 + i * 16 + g + 8]);
            }
#pragma unroll
            for (int j = 0; j < NA; j++) {
                bf[j][0] = __float_as_uint(Bs[kb][wn0 + j * 8 + g]);
                bf[j][1] = __float_as_uint(Bs[kb + 4][wn0 + j * 8 + g]);
            }
#pragma unroll
            for (int i = 0; i < MA; i++)
#pragma unroll
                for (int j = 0; j < NA; j++)
                    asm volatile(
                        "mma.sync.aligned.m16n8k8.row.col.f32.tf32.tf32.f32 "
                        "{%0,%1,%2,%3}, {%4,%5,%6,%7}, {%8,%9}, {%0,%1,%2,%3};"
                        : "+f"(acc[i][j][0]), "+f"(acc[i][j][1]),
                          "+f"(acc[i][j][2]), "+f"(acc[i][j][3])
                        : "r"(af[i][0]), "r"(af[i][1]), "r"(af[i][2]), "r"(af[i][3]),
                          "r"(bf[j][0]), "r"(bf[j][1]));
        }
        __syncthreads();
        if (t + 1 < kTiles) {
            storeSmem();
            __syncthreads();
        }
    }

    // Epilogue: per (i,j,half) -> two consecutive columns (tg*2, tg*2+1)
#pragma unroll
    for (int i = 0; i < MA; i++)
#pragma unroll
        for (int j = 0; j < NA; j++)
#pragma unroll
            for (int h2 = 0; h2 < 2; h2++) {
                const int row = bm + wm0 + i * 16 + g + h2 * 8;
                const int col = bn + wn0 + j * 8 + tg * 2;
                const float v0 = acc[i][j][h2 * 2 + 0];
                const float v1 = acc[i][j][h2 * 2 + 1];
                if constexpr (EPI == 0) {
                    const int b = row >> 11, n = row & (N_ - 1);
                    const int part = col >> 10, c = col & (C_ - 1);
                    const int hh = c >> 6, d = c & 63;
                    const size_t idx = ((size_t)(b * H_ + hh) * N_ + n) * HD_ + d;
                    if (part == 0) {
                        float2 w = make_float2(v0 * 0.125f, v1 * 0.125f);
                        *(float2*)(g_q + idx) = w;
                    } else if (part == 1) {
                        *(float2*)(g_k + idx) = make_float2(v0, v1);
                    } else {
                        *(float2*)(g_v + idx) = make_float2(v0, v1);
                    }
                } else if constexpr (EPI == 1) {
                    const int b = bh >> 4;
                    const float bi0 = (mask[b * N_ + col] != 1) ? -10000.0f : 0.0f;
                    const float bi1 = (mask[b * N_ + col + 1] != 1) ? -10000.0f : 0.0f;
                    float* S = g_s + (size_t)bh * N_ * N_;
                    *(float2*)(S + (size_t)row * N_ + col) = make_float2(v0 + bi0, v1 + bi1);
                } else if constexpr (EPI == 2) {
                    const int b = bh >> 4, hh = bh & 15;
                    *(float2*)(g_ao + (size_t)(b * N_ + row) * C_ + hh * HD_ + col) =
                        make_float2(v0, v1);
                } else {
                    *(float2*)(gC + (size_t)row * N + col) =
                        make_float2(v0 + bias[col], v1 + bias[col + 1]);
                }
            }
}

// ---------------------------------------------------------------------------
// Row softmax over 2048 keys. One block per (b,h,q) row; 8 values/thread.
// ---------------------------------------------------------------------------
__global__ __launch_bounds__(256) void softmax_k() {
    const size_t row = blockIdx.x;
    float* p = g_s + row * N_;
    const int tid = threadIdx.x;
    float4 v0 = *(const float4*)(p + tid * 8);
    float4 v1 = *(const float4*)(p + tid * 8 + 4);

    float m = fmaxf(fmaxf(fmaxf(v0.x, v0.y), fmaxf(v0.z, v0.w)),
                    fmaxf(fmaxf(v1.x, v1.y), fmaxf(v1.z, v1.w)));
#pragma unroll
    for (int o = 16; o > 0; o >>= 1) m = fmaxf(m, __shfl_xor_sync(0xffffffffu, m, o));
    __shared__ float red_m[8];
    __shared__ float red_s[8];
    if ((tid & 31) == 0) red_m[tid >> 5] = m;
    __syncthreads();
    m = red_m[0];
#pragma unroll
    for (int i = 1; i < 8; i++) m = fmaxf(m, red_m[i]);

    v0.x = __expf(v0.x - m); v0.y = __expf(v0.y - m);
    v0.z = __expf(v0.z - m); v0.w = __expf(v0.w - m);
    v1.x = __expf(v1.x - m); v1.y = __expf(v1.y - m);
    v1.z = __expf(v1.z - m); v1.w = __expf(v1.w - m);
    float s = v0.x + v0.y + v0.z + v0.w + v1.x + v1.y + v1.z + v1.w;
#pragma unroll
    for (int o = 16; o > 0; o >>= 1) s += __shfl_xor_sync(0xffffffffu, s, o);
    if ((tid & 31) == 0) red_s[tid >> 5] = s;
    __syncthreads();
    s = red_s[0];
#pragma unroll
    for (int i = 1; i < 8; i++) s += red_s[i];

    float r = 1.0f / s;
    v0.x *= r; v0.y *= r; v0.z *= r; v0.w *= r;
    v1.x *= r; v1.y *= r; v1.z *= r; v1.w *= r;
    *(float4*)(p + tid * 8) = v0;
    *(float4*)(p + tid * 8 + 4) = v1;
}

// ---------------------------------------------------------------------------
extern "C" void kernel_launch(void* const* d_in, const int* in_sizes, int n_in,
                              void* d_out, int out_size) {
    const float* x     = (const float*)d_in[0];
    const int*   mask  = (const int*)d_in[1];
    const float* wqkv  = (const float*)d_in[2];
    const float* wproj = (const float*)d_in[3];
    const float* bproj = (const float*)d_in[4];
    float* out = (float*)d_out;

    // QKV: [8192,1024] @ [1024,3072]
    tf32_gemm<128, 128, 32, 2, 4, false, 0>
        <<<dim3(24, 64, 1), 256>>>(x, wqkv, nullptr, nullptr, nullptr, 8192, 3072, 1024);
    // S = Q @ K^T per (b,h): [2048,64] @ [64,2048]
    tf32_gemm<128, 128, 32, 2, 4, true, 1>
        <<<dim3(16, 16, 64), 256>>>(nullptr, nullptr, mask, nullptr, nullptr, 2048, 2048, 64);
    // softmax rows
    softmax_k<<<BH_ * N_, 256>>>();
    // O = P @ V per (b,h): [2048,2048] @ [2048,64]
    tf32_gemm<128, 64, 32, 4, 2, false, 2>
        <<<dim3(1, 16, 64), 256>>>(nullptr, nullptr, nullptr, nullptr, nullptr, 2048, 64, 2048);
    // proj: [8192,1024] @ [1024,1024] + bias
    tf32_gemm<128, 128, 32, 2, 4, false, 3>
        <<<dim3(8, 64, 1), 256>>>(nullptr, wproj, nullptr, bproj, out, 8192, 1024, 1024);
}